// round 17
// baseline (speedup 1.0000x reference)
#include <cuda_runtime.h>
#include <cuda_bf16.h>
#include <math.h>

// Problem constants
#define BB   32
#define HH   14
#define WW   14
#define CC   32
#define KK   64
#define KS   5
#define OH   10
#define OW   10
#define PP   100      // OH*OW
#define NPOS 196      // H*W
#define MM   800      // KS*KS*C
#define IMG  6272     // NPOS*CC floats per batch
#define SIGB 1229312  // NPOS*NPOS*CC floats per batch of Sigma_in
#define SIGR 6304     // NPOS*CC + CC (diag row stride in floats)
#define PSTR 36       // padded smem stride per position (floats)

// Scratch (device globals)
__device__ float g_dv[BB * PP * KK];       // diag_vals
__device__ float g_S [BB * NPOS * NPOS];   // position-Gram S = X X^T (4.9 MB)

// ---------------- f32x2 packed helpers ----------------
typedef unsigned long long ull;

__device__ __forceinline__ ull f2fma(ull a, ull b, ull c) {
    ull d;
    asm("fma.rn.f32x2 %0, %1, %2, %3;" : "=l"(d) : "l"(a), "l"(b), "l"(c));
    return d;
}
__device__ __forceinline__ ull f2mul(ull a, ull b) {
    ull d;
    asm("mul.rn.f32x2 %0, %1, %2;" : "=l"(d) : "l"(a), "l"(b));
    return d;
}
__device__ __forceinline__ float f2sum(ull v) {
    float lo, hi;
    asm("mov.b64 {%0, %1}, %2;" : "=f"(lo), "=f"(hi) : "l"(v));
    return lo + hi;
}

// ---------------- Kernel A: mu_out + diag_vals ----------------
// grid (5 pt, 2 kh, 32 b) = 320 blocks, 160 threads (5 warps), single wave.
// kk = tid&15, pg = tid>>4 (0..9): thread owns p = {2pg, 2pg+1}, k = {kh*32+kk, kh*32+16+kk}.
// Weights loaded directly from w_mu (channel-quad gather) per kernel-row phase.
__global__ __launch_bounds__(160, 3) void k_mu_diag(const float* __restrict__ mu_in,
                                                    const float* __restrict__ Sg,
                                                    const float* __restrict__ w_mu,
                                                    const float* __restrict__ w_sigma,
                                                    float* __restrict__ out_mu) {
    __shared__ __align__(16) float4 s_w [5 * 256];   // [j(5)][c4(8)][k2(2)][kk(16)]
    __shared__ __align__(16) float  s_mu[84 * PSTR]; // 6 rows x 14 pos, padded
    __shared__ __align__(16) float  s_ds[84 * PSTR];
    __shared__ float s_S[84];
    __shared__ float s_tr[20];

    int tid = threadIdx.x;
    int pt  = blockIdx.x;            // output rows 2pt, 2pt+1
    int kh  = blockIdx.y;            // k half
    int b   = blockIdx.z;
    int kk  = tid & 15;
    int pg  = tid >> 4;              // 0..9

    float4 pf[8];

    // --- prefetch phase 0 (kernel row i=0) directly from w_mu ---
    #pragma unroll
    for (int l = 0; l < 8; l++) {
        int f  = l * 160 + tid;
        int j  = f >> 8;
        int rr = f & 255;
        int c4 = rr >> 5;
        int kx = rr & 31;
        const float* wp = w_mu + ((j * 32 + 4 * c4) * KK) + kh * 32 + kx;
        pf[l].x = __ldg(wp);
        pf[l].y = __ldg(wp + KK);
        pf[l].z = __ldg(wp + 2 * KK);
        pf[l].w = __ldg(wp + 3 * KK);
    }

    // --- fused load: mu tile (6 image rows) + Sigma-diag gather + channel sums ---
    {
        const float4* msrc = reinterpret_cast<const float4*>(mu_in + b * IMG + pt * 28 * 32);
        const float*  sb   = Sg + b * SIGB;
        for (int t = tid; t < 672; t += 160) {
            int pos_l = t >> 3;                      // 0..83
            int c4    = t & 7;
            float4 mv = msrc[t];
            *reinterpret_cast<float4*>(s_mu + pos_l * PSTR + c4 * 4) = mv;
            int pos = pt * 28 + pos_l;
            float4 sg = *reinterpret_cast<const float4*>(sb + pos * SIGR + c4 * 4);
            *reinterpret_cast<float4*>(s_ds + pos_l * PSTR + c4 * 4) = sg;
            float part = sg.x + sg.y + sg.z + sg.w;
            part += __shfl_down_sync(0xffffffffu, part, 4, 8);
            part += __shfl_down_sync(0xffffffffu, part, 2, 8);
            part += __shfl_down_sync(0xffffffffu, part, 1, 8);
            if (c4 == 0) s_S[pos_l] = part;
        }
    }
    __syncthreads();

    // --- trace per patch (20 p's) ---
    if (tid < 20) {
        int pr = tid / 10, pc = tid % 10;
        float s = 0.f;
        #pragma unroll
        for (int i = 0; i < KS; i++)
            #pragma unroll
            for (int j = 0; j < KS; j++)
                s += s_S[(pr + i) * 14 + pc + j];
        s_tr[tid] = s;
    }

    // p bases for this thread's 2 patches
    int pbase[2];
    #pragma unroll
    for (int jp = 0; jp < 2; jp++) {
        int pl = pg * 2 + jp;                        // 0..19
        int pr = pl / 10, pc = pl % 10;
        pbase[jp] = (pr * 14 + pc) * PSTR;
    }

    ull accM[2][2], accV[2][2];
    #pragma unroll
    for (int jp = 0; jp < 2; jp++) {
        accM[jp][0] = 0ull; accM[jp][1] = 0ull;
        accV[jp][0] = 0ull; accV[jp][1] = 0ull;
    }

    const ulonglong2* s_w2 = reinterpret_cast<const ulonglong2*>(s_w);

    // --- 5 phases (kernel rows), 5 taps each ---
    #pragma unroll 1
    for (int i = 0; i < KS; i++) {
        // store stage i, prefetch stage i+1 from w_mu
        #pragma unroll
        for (int l = 0; l < 8; l++)
            s_w[l * 160 + tid] = pf[l];
        if (i + 1 < KS) {
            const float* wrow = w_mu + (i + 1) * 5 * 32 * KK + kh * 32;
            #pragma unroll
            for (int l = 0; l < 8; l++) {
                int f  = l * 160 + tid;
                int j  = f >> 8;
                int rr = f & 255;
                int c4 = rr >> 5;
                int kx = rr & 31;
                const float* wp = wrow + (j * 32 + 4 * c4) * KK + kx;
                pf[l].x = __ldg(wp);
                pf[l].y = __ldg(wp + KK);
                pf[l].z = __ldg(wp + 2 * KK);
                pf[l].w = __ldg(wp + 3 * KK);
            }
        }
        __syncthreads();                 // stage i visible

        int rowoff = i * 14 * PSTR;
        #pragma unroll
        for (int j = 0; j < KS; j++) {
            int sh = rowoff + j * PSTR;
            #pragma unroll
            for (int c4 = 0; c4 < 8; c4++) {
                ulonglong2 w0 = s_w2[(j * 8 + c4) * 32 + kk];        // k = kh*32 + kk
                ulonglong2 w1 = s_w2[(j * 8 + c4) * 32 + 16 + kk];   // k = kh*32 + 16 + kk
                ull s0A = f2mul(w0.x, w0.x);
                ull s0B = f2mul(w0.y, w0.y);
                ull s1A = f2mul(w1.x, w1.x);
                ull s1B = f2mul(w1.y, w1.y);
                #pragma unroll
                for (int jp = 0; jp < 2; jp++) {
                    int off = pbase[jp] + sh + c4 * 4;
                    ulonglong2 a = *reinterpret_cast<const ulonglong2*>(s_mu + off);
                    ulonglong2 d = *reinterpret_cast<const ulonglong2*>(s_ds + off);
                    accM[jp][0] = f2fma(a.x, w0.x, accM[jp][0]);
                    accM[jp][0] = f2fma(a.y, w0.y, accM[jp][0]);
                    accM[jp][1] = f2fma(a.x, w1.x, accM[jp][1]);
                    accM[jp][1] = f2fma(a.y, w1.y, accM[jp][1]);
                    accV[jp][0] = f2fma(d.x, s0A, accV[jp][0]);
                    accV[jp][0] = f2fma(d.y, s0B, accV[jp][0]);
                    accV[jp][1] = f2fma(d.x, s1A, accV[jp][1]);
                    accV[jp][1] = f2fma(d.y, s1B, accV[jp][1]);
                }
            }
        }
        if (i + 1 < KS) __syncthreads(); // stage reads done before next overwrite
    }

    int kg0 = kh * 32 + kk;
    int kg1 = kh * 32 + 16 + kk;
    float sp0 = log1pf(expf(w_sigma[kg0]));
    float sp1 = log1pf(expf(w_sigma[kg1]));
    #pragma unroll
    for (int jp = 0; jp < 2; jp++) {
        int pl = pg * 2 + jp;
        int p  = pt * 20 + pl;
        int base = (b * PP + p) * KK;
        float tr = s_tr[pl];
        out_mu[base + kg0] = f2sum(accM[jp][0]);
        out_mu[base + kg1] = f2sum(accM[jp][1]);
        g_dv[base + kg0]   = f2sum(accV[jp][0]) + sp0 * tr;
        g_dv[base + kg1]   = f2sum(accV[jp][1]) + sp1 * tr;
    }
}

// ---------------- Kernel B: S = X X^T (wide) ----------------
__global__ __launch_bounds__(256) void k_gram_s(const float* __restrict__ mu_in) {
    __shared__ __align__(16) float2 s_yc[16 * 200];   // [c2][pos], padded

    int tid = threadIdx.x;
    int b   = blockIdx.y;
    int x0  = blockIdx.x * 28;
    const float* mb = mu_in + b * IMG;

    for (int t = tid; t < 16 * NPOS; t += 256) {
        int c2 = t & 15, pos = t >> 4;
        s_yc[c2 * 200 + pos] = *reinterpret_cast<const float2*>(mb + pos * 32 + c2 * 2);
    }
    __syncthreads();

    int lane = tid & 31, wrp = tid >> 5;
    float* Sb = g_S + b * (NPOS * NPOS);

    #pragma unroll 1
    for (int r = 0; r < 4; r++) {
        int xl = wrp + 8 * r;
        if (xl >= 28) break;
        int x = x0 + xl;

        ull xc[16];
        #pragma unroll
        for (int c2 = 0; c2 < 16; c2++)
            xc[c2] = *reinterpret_cast<const ull*>(s_yc + c2 * 200 + x);   // broadcast

        #pragma unroll 1
        for (int m = 0; m < 4; m++) {
            int pr = lane + 32 * m;
            if (pr >= 98) break;
            int y0 = 2 * pr;
            ull acc0 = 0ull, acc1 = 0ull;
            #pragma unroll
            for (int c2 = 0; c2 < 16; c2++) {
                ulonglong2 v = *reinterpret_cast<const ulonglong2*>(s_yc + c2 * 200 + y0);
                acc0 = f2fma(xc[c2], v.x, acc0);
                acc1 = f2fma(xc[c2], v.y, acc1);
            }
            float2 rr;
            rr.x = f2sum(acc0);
            rr.y = f2sum(acc1);
            *reinterpret_cast<float2*>(Sb + x * NPOS + y0) = rr;
        }
    }
}

// ---------------- Kernel C1: expand off-diagonal rows (q != p), G computed inline ----------------
__global__ __launch_bounds__(256) void k_expand_off(const float* __restrict__ w_sigma,
                                                    float* __restrict__ out) {
    __shared__ float  s_g[PP];
    __shared__ float4 s_sp[16];

    int tid = threadIdx.x;
    int p = blockIdx.x, b = blockIdx.y;
    int bp = b * PP + p;
    int pr = p / 10, pc = p % 10;

    // inline Gram row: G[p][q] = 25-shift diagonal sum of S
    if (tid < PP) {
        int q  = tid;
        int qr = q / 10, qc = q % 10;
        const float* s = g_S + b * (NPOS * NPOS) + (pr * 14 + pc) * NPOS + (qr * 14 + qc);
        float acc = 0.f;
        #pragma unroll
        for (int i = 0; i < KS; i++)
            #pragma unroll
            for (int j = 0; j < KS; j++)
                acc += __ldg(s + (i * 14 + j) * (NPOS + 1));
        s_g[q] = acc;
    }
    if (tid >= 128 && tid < 144) {
        int k4 = (tid - 128) * 4;
        float4 sp;
        sp.x = log1pf(expf(w_sigma[k4]));
        sp.y = log1pf(expf(w_sigma[k4 + 1]));
        sp.z = log1pf(expf(w_sigma[k4 + 2]));
        sp.w = log1pf(expf(w_sigma[k4 + 3]));
        s_sp[tid - 128] = sp;
    }
    __syncthreads();

    float* orow = out + BB * PP * KK + bp * (PP * KK);

    #pragma unroll
    for (int it = 0; it < 7; it++) {
        int v = tid + it * 256;
        if (v < PP * 16) {
            int q = v >> 4;
            if (q == p) continue;                    // diagonal row handled elsewhere
            int kc = v & 15, k4 = kc * 4;
            float g = s_g[q];
            float4 sp = s_sp[kc];
            float4 r;
            r.x = sp.x * g; r.y = sp.y * g; r.z = sp.z * g; r.w = sp.w * g;
            r.x = isfinite(r.x) ? r.x : 0.f;
            r.y = isfinite(r.y) ? r.y : 0.f;
            r.z = isfinite(r.z) ? r.z : 0.f;
            r.w = isfinite(r.w) ? r.w : 0.f;
            if (q == k4)     r.x = fabsf(r.x);
            if (q == k4 + 1) r.y = fabsf(r.y);
            if (q == k4 + 2) r.z = fabsf(r.z);
            if (q == k4 + 3) r.w = fabsf(r.w);
            *reinterpret_cast<float4*>(orow + 4 * v) = r;
        }
    }
}

// ---------------- Kernel C2: expand diagonal rows (q == p), warp-per-row ----------------
// grid 100 blocks x 256 thr (8 warps); each warp handles 4 bp rows.
__global__ __launch_bounds__(256) void k_expand_diag(const float* __restrict__ w_sigma,
                                                     float* __restrict__ out) {
    __shared__ float4 s_sp[16];

    int tid  = threadIdx.x;
    int lane = tid & 31;
    int wrp  = tid >> 5;

    if (tid < 16) {
        int k4 = tid * 4;
        float4 sp;
        sp.x = log1pf(expf(w_sigma[k4]));
        sp.y = log1pf(expf(w_sigma[k4 + 1]));
        sp.z = log1pf(expf(w_sigma[k4 + 2]));
        sp.w = log1pf(expf(w_sigma[k4 + 3]));
        s_sp[tid] = sp;
    }
    __syncthreads();

    #pragma unroll
    for (int it = 0; it < 4; it++) {
        int bp = (blockIdx.x * 8 + wrp) * 4 + it;    // 0..3199
        int b = bp / PP, p = bp - b * PP;
        int pr = p / 10, pc = p % 10;

        // G[p][p]: 25-term diagonal sum, one term per lane (<25), shuffle-reduce
        float part = 0.f;
        if (lane < 25) {
            int i = lane / 5, j = lane % 5;
            part = __ldg(g_S + b * (NPOS * NPOS) + (pr * 14 + pc) * (NPOS + 1)
                         + (i * 14 + j) * (NPOS + 1));
        }
        part += __shfl_down_sync(0xffffffffu, part, 16);
        part += __shfl_down_sync(0xffffffffu, part, 8);
        part += __shfl_down_sync(0xffffffffu, part, 4);
        part += __shfl_down_sync(0xffffffffu, part, 2);
        part += __shfl_down_sync(0xffffffffu, part, 1);
        float g = __shfl_sync(0xffffffffu, part, 0);

        if (lane < 16) {
            int k4 = lane * 4;
            float4 sp  = s_sp[lane];
            float4 dv4 = *reinterpret_cast<const float4*>(g_dv + bp * KK + k4);
            float4 r;
            r.x = sp.x * g + dv4.x;
            r.y = sp.y * g + dv4.y;
            r.z = sp.z * g + dv4.z;
            r.w = sp.w * g + dv4.w;
            r.x = isfinite(r.x) ? r.x : 0.f;
            r.y = isfinite(r.y) ? r.y : 0.f;
            r.z = isfinite(r.z) ? r.z : 0.f;
            r.w = isfinite(r.w) ? r.w : 0.f;
            if (p == k4)     r.x = fabsf(r.x);
            if (p == k4 + 1) r.y = fabsf(r.y);
            if (p == k4 + 2) r.z = fabsf(r.z);
            if (p == k4 + 3) r.w = fabsf(r.w);
            float* orow = out + BB * PP * KK + bp * (PP * KK) + p * KK;
            *reinterpret_cast<float4*>(orow + k4) = r;
        }
    }
}

// ---------------- launch ----------------
extern "C" void kernel_launch(void* const* d_in, const int* in_sizes, int n_in,
                              void* d_out, int out_size) {
    const float* mu_in    = (const float*)d_in[0];
    const float* Sigma_in = (const float*)d_in[1];
    const float* w_mu     = (const float*)d_in[2];
    const float* w_sigma  = (const float*)d_in[3];
    float* out = (float*)d_out;

    static cudaStream_t s2 = nullptr;
    static cudaEvent_t  eFork = nullptr, eJoin = nullptr;
    if (s2 == nullptr) {
        cudaStreamCreateWithFlags(&s2, cudaStreamNonBlocking);
        cudaEventCreateWithFlags(&eFork, cudaEventDisableTiming);
        cudaEventCreateWithFlags(&eJoin, cudaEventDisableTiming);
    }

    // Phase 1 (serial, LDS-bound): position-Gram S
    k_gram_s<<<dim3(7, BB), 256>>>(mu_in);

    // Phase 2: DRAM-bound expand_off on side stream CONCURRENT with LDS-bound mu_diag
    cudaEventRecord(eFork, 0);
    cudaStreamWaitEvent(s2, eFork, 0);
    k_expand_off<<<dim3(PP, BB), 256, 0, s2>>>(w_sigma, out);
    cudaEventRecord(eJoin, s2);

    k_mu_diag<<<dim3(5, 2, BB), 160>>>(mu_in, Sigma_in, w_mu, w_sigma, out);

    // Phase 3: diagonal rows (needs g_dv from main + g_S; after join)
    cudaStreamWaitEvent(0, eJoin, 0);
    k_expand_diag<<<100, 256>>>(w_sigma, out);
}